// round 17
// baseline (speedup 1.0000x reference)
#include <cuda_runtime.h>
#include <cuda_fp16.h>
#include <cstdint>

#define NODES_MAX 100000
#define M_PAD 100096            // round up to 128
#define IN_DIM 128
#define HIDDEN 128

// Scratch (device globals: no allocations allowed).
__device__ __half g_Yh[(size_t)M_PAD * 256];     // per-node [A+b1 | B] features, fp16 (51 MB)
__device__ __half g_Wh[IN_DIM * 256];            // repacked W1 [k][o] fp16
__device__ int g_idx_is64;

// ---------------------------------------------------------------------------
// Prep: blocks 0..3 do a smem-tiled transpose of W1 -> Wh (both global sides
// coalesced; scatter absorbed in shared memory). Block 4 detects index width.
// Block b owns o' in [b*64, b*64+64), where o'<128 -> W1[o'][k] (src half),
// o'>=128 -> W1[o'-128][128+k] (dst half). Wh[k][o'] fp16.
// smem tile [64 o][128 k], row stride 129 halves (odd word stride -> the
// column gather in phase 2 hits distinct banks).
// ---------------------------------------------------------------------------
#define TP_STRIDE 129

__global__ void prep_kernel(const float* __restrict__ W1,
                            const void* __restrict__ ei, int E, int M) {
    if (blockIdx.x == 4) {
        __shared__ int bad;
        if (threadIdx.x == 0) bad = 0;
        __syncthreads();
        const long long* p = (const long long*)ei;
        int n = E < 512 ? E : 512;
        for (int i = threadIdx.x; i < n; i += blockDim.x) {
            long long v = p[i];
            if (v < 0 || v >= (long long)M) atomicOr(&bad, 1);
        }
        __syncthreads();
        if (threadIdx.x == 0) g_idx_is64 = bad ? 0 : 1;
        return;
    }

    __shared__ __half sm[64 * TP_STRIDE];
    const int t = threadIdx.x;
    const int o0 = blockIdx.x * 64;

    // Phase 1: coalesced loads of W1 rows (4 threads per o-row, 8 float4 each).
    const int o_loc = t >> 2;            // 0..63
    const int q = t & 3;                 // k quarter: k in [q*32, q*32+32)
    const int o = o0 + o_loc;
    const float* src = W1 + (o < 128 ? (size_t)o * 256 : (size_t)(o - 128) * 256 + 128);
#pragma unroll
    for (int j = 0; j < 8; j++) {
        int k = q * 32 + j * 4;
        float4 v = *(const float4*)(src + k);
        __half* dst = sm + o_loc * TP_STRIDE + k;
        dst[0] = __float2half_rn(v.x);
        dst[1] = __float2half_rn(v.y);
        dst[2] = __float2half_rn(v.z);
        dst[3] = __float2half_rn(v.w);
    }
    __syncthreads();

    // Phase 2: column gather from smem, coalesced uint4 stores to Wh.
    // 8 threads per k-row (kq), each covers 8 consecutive o (16B).
    const int kq = t & 7;
    const int kr = t >> 3;               // 0..31
#pragma unroll
    for (int r = 0; r < 4; r++) {
        int k = r * 32 + kr;
        __half tmp[8];
#pragma unroll
        for (int j = 0; j < 8; j++)
            tmp[j] = sm[(kq * 8 + j) * TP_STRIDE + k];
        *(uint4*)(g_Wh + (size_t)k * 256 + o0 + kq * 8) = *(uint4*)tmp;
    }
}

// ---------------------------------------------------------------------------
// GEMM helpers.
// ---------------------------------------------------------------------------
__device__ __forceinline__ void ldsm4(uint32_t* r, uint32_t addr) {
    asm volatile("ldmatrix.sync.aligned.m8n8.x4.shared.b16 {%0,%1,%2,%3}, [%4];"
                 : "=r"(r[0]), "=r"(r[1]), "=r"(r[2]), "=r"(r[3]) : "r"(addr));
}
__device__ __forceinline__ void ldsm4t(uint32_t* r, uint32_t addr) {
    asm volatile("ldmatrix.sync.aligned.m8n8.x4.trans.shared.b16 {%0,%1,%2,%3}, [%4];"
                 : "=r"(r[0]), "=r"(r[1]), "=r"(r[2]), "=r"(r[3]) : "r"(addr));
}
__device__ __forceinline__ void cp16(uint32_t saddr, const void* gptr) {
    asm volatile("cp.async.cg.shared.global [%0], [%1], 16;" :: "r"(saddr), "l"(gptr));
}
__device__ __forceinline__ void cp_commit() {
    asm volatile("cp.async.commit_group;");
}
template <int N> __device__ __forceinline__ void cp_wait() {
    asm volatile("cp.async.wait_group %0;" :: "n"(N));
}
__device__ __forceinline__ uint4 cvt8(float4 x, float4 y) {
    __half2 h0 = __floats2half2_rn(x.x, x.y);
    __half2 h1 = __floats2half2_rn(x.z, x.w);
    __half2 h2 = __floats2half2_rn(y.x, y.y);
    __half2 h3 = __floats2half2_rn(y.z, y.w);
    uint4 r;
    r.x = *(uint32_t*)&h0; r.y = *(uint32_t*)&h1;
    r.z = *(uint32_t*)&h2; r.w = *(uint32_t*)&h3;
    return r;
}
#define MMA16816(d, a, b)                                                      \
    asm volatile(                                                              \
        "mma.sync.aligned.m16n8k16.row.col.f32.f16.f16.f32 "                   \
        "{%0,%1,%2,%3}, {%4,%5,%6,%7}, {%8,%9}, {%0,%1,%2,%3};"                \
        : "+f"(d[0]), "+f"(d[1]), "+f"(d[2]), "+f"(d[3])                       \
        : "r"(a[0]), "r"(a[1]), "r"(a[2]), "r"(a[3]), "r"(b[0]), "r"(b[1]))

// ---------------------------------------------------------------------------
// Tensor-core GEMM with fused fp32->fp16 A conversion and fused b1 bias:
//   Yh[M x 256] = cvt(z)[M x 128] @ Wh[128 x 256]  (+ b1 on cols 0..127)
// Identical to validated R11..R16 kernel.
// ---------------------------------------------------------------------------
#define STAGE_BYTES 12288

__global__ __launch_bounds__(256, 3) void node_gemm_f16(const float* __restrict__ z,
                                                        const float* __restrict__ b1,
                                                        int M) {
    __shared__ __align__(16) unsigned char smem[4 * STAGE_BYTES];

    const int tid = threadIdx.x;
    const int lane = tid & 31;
    const int w = tid >> 5;
    const int wm = w & 1;          // 2 warps along M (32 rows each)
    const int wn = w >> 1;         // 4 warps along N (32 cols each)
    const int row0 = blockIdx.x * 64;
    const int col0 = blockIdx.y * 128;

    const uint32_t sbase = (uint32_t)__cvta_generic_to_shared(&smem[0]);

    // ---- B async store mapping ----
    const int bk = tid >> 3;
    const int bs = tid & 7;
    const uint32_t sB0 = sbase + 4096 + bk * 256 + (((bs) << 4) ^ ((bk & 7) << 4));
    const uint32_t sB1 = sbase + 4096 + bk * 256 + (((bs + 8) << 4) ^ ((bk & 7) << 4));
    const __half* BgBase = g_Wh + (size_t)bk * 256 + col0 + bs * 8;

#pragma unroll
    for (int c = 0; c < 4; c++) {
        uint32_t st = c * STAGE_BYTES;
        cp16(sB0 + st, BgBase + (size_t)c * 32 * 256);
        cp16(sB1 + st, BgBase + (size_t)c * 32 * 256 + 64);
        cp_commit();
    }

    // ---- A store mapping: row=tid>>2, 16B slot=tid&3 ----
    const int ar = tid >> 2;
    const int as = tid & 3;
    const int aByte = ar * 64 + (((as) ^ ((ar >> 1) & 3)) << 4);
    const int arow = row0 + ar;
    const float* Az = z + (size_t)(arow < M ? arow : 0) * 128 + as * 8;

    float4 rfa, rfb;
    rfa = *(const float4*)(Az);          // chunk 0
    rfb = *(const float4*)(Az + 4);
    *(uint4*)(&smem[0 * STAGE_BYTES + aByte]) = cvt8(rfa, rfb);
    rfa = *(const float4*)(Az + 32);     // chunk 1
    rfb = *(const float4*)(Az + 36);

    // ---- ldmatrix per-thread offsets (within a stage) ----
    uint32_t aOff[2];
#pragma unroll
    for (int mi = 0; mi < 2; mi++) {
        int r = wm * 32 + mi * 16 + (lane & 15);
        int slot = (lane >> 4) ^ ((r >> 1) & 3);
        aOff[mi] = r * 64 + slot * 16;              // kk=1 -> ^0x20
    }
    uint32_t bOff[2];
    {
        int k = lane & 15;
#pragma unroll
        for (int ni = 0; ni < 2; ni++) {
            int nb = wn * 64 + ni * 32 + ((lane >> 4) & 1) * 16;
            bOff[ni] = 4096 + k * 256 + (nb ^ ((k & 7) << 4));  // kk=1 -> +4096
        }
    }

    float acc[2][4][4];
#pragma unroll
    for (int i = 0; i < 2; i++)
#pragma unroll
        for (int j = 0; j < 4; j++)
#pragma unroll
            for (int t = 0; t < 4; t++) acc[i][j][t] = 0.0f;

#define CHUNK(c)                                                               \
    {                                                                          \
        cp_wait<3 - (c)>();                                                    \
        __syncthreads();                                                       \
        if ((c) < 3) {                                                         \
            *(uint4*)(&smem[((c) + 1) * STAGE_BYTES + aByte]) = cvt8(rfa, rfb);\
            if ((c) < 2) {                                                     \
                rfa = *(const float4*)(Az + ((c) + 2) * 32);                   \
                rfb = *(const float4*)(Az + ((c) + 2) * 32 + 4);               \
            }                                                                  \
        }                                                                      \
        const uint32_t buf = sbase + (c) * STAGE_BYTES;                        \
        _Pragma("unroll")                                                      \
        for (int kk = 0; kk < 2; kk++) {                                       \
            uint32_t a[2][4], b[4][2];                                         \
            _Pragma("unroll")                                                  \
            for (int mi = 0; mi < 2; mi++)                                     \
                ldsm4(a[mi], buf + (kk ? (aOff[mi] ^ 0x20) : aOff[mi]));       \
            _Pragma("unroll")                                                  \
            for (int ni = 0; ni < 2; ni++) {                                   \
                uint32_t r[4];                                                 \
                ldsm4t(r, buf + bOff[ni] + (kk ? 4096 : 0));                   \
                b[ni * 2 + 0][0] = r[0]; b[ni * 2 + 0][1] = r[1];              \
                b[ni * 2 + 1][0] = r[2]; b[ni * 2 + 1][1] = r[3];              \
            }                                                                  \
            _Pragma("unroll")                                                  \
            for (int mi = 0; mi < 2; mi++)                                     \
                _Pragma("unroll")                                              \
                for (int ni = 0; ni < 4; ni++)                                 \
                    MMA16816(acc[mi][ni], a[mi], b[ni]);                       \
        }                                                                      \
    }

    CHUNK(0)
    CHUNK(1)
    CHUNK(2)
    CHUNK(3)
#undef CHUNK

    // epilogue: fp32 acc (+ b1 on the src half, i.e. blockIdx.y==0) -> fp16 Y
    const int tr = lane >> 2;
    const int tc = (lane & 3) * 2;
    float2 bias[4];
#pragma unroll
    for (int ni = 0; ni < 4; ni++) {
        if (col0 == 0) {
            bias[ni] = *(const float2*)(b1 + wn * 32 + ni * 8 + tc);
        } else {
            bias[ni] = make_float2(0.f, 0.f);
        }
    }
#pragma unroll
    for (int mi = 0; mi < 2; mi++) {
#pragma unroll
        for (int ni = 0; ni < 4; ni++) {
            int gr = row0 + wm * 32 + mi * 16 + tr;
            int gc = col0 + wn * 32 + ni * 8 + tc;
            if (gr < M) {
                __half2 v0 = __floats2half2_rn(acc[mi][ni][0] + bias[ni].x,
                                               acc[mi][ni][1] + bias[ni].y);
                *(__half2*)(g_Yh + (size_t)gr * 256 + gc) = v0;
            }
            if (gr + 8 < M) {
                __half2 v1 = __floats2half2_rn(acc[mi][ni][2] + bias[ni].x,
                                               acc[mi][ni][3] + bias[ni].y);
                *(__half2*)(g_Yh + (size_t)(gr + 8) * 256 + gc) = v1;
            }
        }
    }
}

// ---------------------------------------------------------------------------
// Per-edge stage v6 (identical to validated R14/R16): 8 lanes per edge,
// W2 packed as 8x half2, __launch_bounds__(256,5) for 40 warps/SM.
// ---------------------------------------------------------------------------
__global__ __launch_bounds__(256, 5) void edge_kernel(
        const void* __restrict__ ei,
        const float* __restrict__ W2,
        const float* __restrict__ b2,
        float* __restrict__ out, int E, int M) {
    const int lane = threadIdx.x & 31;
    const int octet = lane >> 3;      // which edge of the 4 in the warp
    const int oi = lane & 7;          // unit group within the edge

    int gw = (blockIdx.x * blockDim.x + threadIdx.x) >> 5;
    const int nw = (gridDim.x * blockDim.x) >> 5;

    // Per-lane W2 slice: units [16*oi, 16*oi+16), packed as 8 half2.
    __half2 w2h[8];
#pragma unroll
    for (int j = 0; j < 4; j++) {
        float4 t = *(const float4*)(W2 + oi * 16 + j * 4);
        w2h[j * 2 + 0] = __floats2half2_rn(t.x, t.y);
        w2h[j * 2 + 1] = __floats2half2_rn(t.z, t.w);
    }
    const float pp0 = b2[0] * 0.125f;   // b2 distributed over 8 lanes (exact /8)
    const int is64 = g_idx_is64;
    const __half2 z2 = __float2half2_rn(0.0f);

    const long long* __restrict__ src64 = (const long long*)ei;
    const long long* __restrict__ dst64 = src64 + E;
    const int* __restrict__ src32 = (const int*)ei;
    const int* __restrict__ dst32 = src32 + E;

    for (int e0 = gw * 8; e0 < E; e0 += nw * 8) {
        // group g handles edge e0 + g*4 + octet
        int s[2], d[2], ee[2];
#pragma unroll
        for (int g = 0; g < 2; g++) {
            int e = e0 + g * 4 + octet;
            ee[g] = e;
            if (e >= E) e = E - 1;
            int ss, dd;
            if (is64) { ss = (int)src64[e]; dd = (int)dst64[e]; }
            else      { ss = src32[e];      dd = dst32[e]; }
            if ((unsigned)ss >= (unsigned)M) ss = 0;
            if ((unsigned)dd >= (unsigned)M) dd = 0;
            s[g] = ss; d[g] = dd;
        }

        // Issue all 8 gathers before any compute.
        uint4 va[2][2], vb[2][2];
#pragma unroll
        for (int g = 0; g < 2; g++) {
            const __half* ps = g_Yh + (size_t)s[g] * 256 + oi * 16;
            const __half* pd = g_Yh + (size_t)d[g] * 256 + 128 + oi * 16;
            va[g][0] = *(const uint4*)(ps);
            va[g][1] = *(const uint4*)(ps + 8);
            vb[g][0] = *(const uint4*)(pd);
            vb[g][1] = *(const uint4*)(pd + 8);
        }

#pragma unroll
        for (int g = 0; g < 2; g++) {
            float pp = pp0;
            const uint32_t* ua = (const uint32_t*)&va[g][0];
            const uint32_t* ub = (const uint32_t*)&vb[g][0];
#pragma unroll
            for (int j = 0; j < 8; j++) {
                __half2 h = __hmax2(__hadd2(*(const __half2*)&ua[j],
                                            *(const __half2*)&ub[j]), z2);
                float2 f = __half22float2(h);
                float2 wf = __half22float2(w2h[j]);
                pp = fmaf(f.x, wf.x, pp);
                pp = fmaf(f.y, wf.y, pp);
            }
            // butterfly over the octet (offsets 4,2,1 stay within 8 lanes)
            pp += __shfl_xor_sync(0xffffffffu, pp, 4);
            pp += __shfl_xor_sync(0xffffffffu, pp, 2);
            pp += __shfl_xor_sync(0xffffffffu, pp, 1);

            if (oi == 0 && ee[g] < E) out[ee[g]] = pp;
        }
    }
}

// ---------------------------------------------------------------------------
extern "C" void kernel_launch(void* const* d_in, const int* in_sizes, int n_in,
                              void* d_out, int out_size) {
    const float* z  = (const float*)d_in[0];
    const void*  ei = d_in[1];
    const float* W1 = (const float*)d_in[2];
    const float* b1 = (const float*)d_in[3];
    const float* W2 = (const float*)d_in[4];
    const float* b2 = (const float*)d_in[5];
    float*       out = (float*)d_out;

    int M = in_sizes[0] / IN_DIM;
    if (M > NODES_MAX) M = NODES_MAX;
    int E = in_sizes[1] / 2;

    // 4 smem-tiled transpose blocks + 1 detect block.
    prep_kernel<<<5, 256>>>(W1, ei, E, M);

    dim3 ggrid(M_PAD / 64, 2);
    node_gemm_f16<<<ggrid, 256>>>(z, b1, M);

    edge_kernel<<<740, 256>>>(ei, W2, b2, out, E, M);
}